// round 1
// baseline (speedup 1.0000x reference)
#include <cuda_runtime.h>
#include <cstdint>

// GPTQ 4-bit quantized linear: out[64,14336] = x[64,4096] @ dequant(W) + bias
// Round 1: FFMA2 (fp32x2) scalar GEMM with smem-staged dequant, split-K=4,
// deterministic partial-sum scratch + reduce kernel.

#define IN_DIM   4096
#define OUT_DIM  14336
#define BATCH    64
#define KSPLIT   4
#define TILE_N   128
#define K_TILE   128     // == group size; scales/zeros constant per tile
#define THREADS  256

// split-K partial sums: [KSPLIT][BATCH][OUT_DIM] fp32 (14.7 MB, static scratch)
__device__ float g_part[KSPLIT * BATCH * OUT_DIM];

__device__ __forceinline__ unsigned long long pack2dup(float v) {
    unsigned long long r;
    unsigned u = __float_as_uint(v);
    asm("mov.b64 %0, {%1, %1};" : "=l"(r) : "r"(u));
    return r;
}

__device__ __forceinline__ void ffma2(unsigned long long& d,
                                      unsigned long long a,
                                      unsigned long long b) {
    // packed fp32x2 FMA (sm_100+): d = a*b + d on both 32-bit lanes
    asm("fma.rn.f32x2 %0, %1, %2, %0;" : "+l"(d) : "l"(a), "l"(b));
}

extern __shared__ float smem[];

__global__ __launch_bounds__(THREADS, 2)
void gptq_gemm(const float* __restrict__ x,
               const int*   __restrict__ qweight,
               const int*   __restrict__ qzeros,
               const float* __restrict__ scales,
               const int*   __restrict__ g_idx)
{
    float* ws = smem;                      // [K_TILE][TILE_N] dequantized W (64 KB)
    float* xs = ws + K_TILE * TILE_N;      // [BATCH][K_TILE] x tile (32 KB)

    const int tid   = threadIdx.x;
    const int j0    = blockIdx.x * TILE_N;
    const int split = blockIdx.y;
    const int kbase = split * (IN_DIM / KSPLIT);

    const int c  = tid & 31;   // column thread: owns cols j0 + 4c .. +3
    const int r  = tid >> 5;   // row thread:    owns rows 8r .. 8r+7
    const int rb = r * 8;

    unsigned long long acc[8][2];
    #pragma unroll
    for (int i = 0; i < 8; i++) { acc[i][0] = 0ull; acc[i][1] = 0ull; }

    const int NTILES = (IN_DIM / KSPLIT) / K_TILE;   // 8
    for (int t = 0; t < NTILES; ++t) {
        const int k0 = kbase + t * K_TILE;
        const int g  = g_idx[k0];   // group constant across the aligned 128-chunk

        // ---- stage x tile: xs[b][k] (coalesced float4, conflict-free) ----
        #pragma unroll
        for (int it = 0; it < (BATCH * K_TILE / 4) / THREADS; ++it) {  // 8
            int idx = tid + THREADS * it;     // 0..2047 float4 slots
            int b   = idx >> 5;               // 32 float4 per row
            int kq  = idx & 31;
            *(float4*)(xs + b * K_TILE + kq * 4) =
                *(const float4*)(x + b * IN_DIM + k0 + kq * 4);
        }

        // ---- dequant W tile into smem: ws[k][j] = s * (w - z)  (exact) ----
        #pragma unroll
        for (int it = 0; it < (K_TILE / 8) * TILE_N / THREADS; ++it) {  // 8
            int widx = tid + THREADS * it;    // 0..2047 packed words
            int j    = widx & (TILE_N - 1);
            int krow = widx >> 7;             // 0..15
            int gj   = j0 + j;
            unsigned q  = (unsigned)qweight[(k0 / 8 + krow) * OUT_DIM + gj];
            float    s  = scales[g * OUT_DIM + gj];
            unsigned zq = (unsigned)qzeros[g * (OUT_DIM / 8) + (gj >> 3)];
            float    z  = (float)(((zq >> ((gj & 7) * 4)) & 15u) + 1u);
            // magic-number int->float; subtract BEFORE scaling (Sterbenz-exact
            // difference of small ints) to match reference rounding exactly.
            float bz = 8388608.0f + z;
            float* wrow = ws + (krow * 8) * TILE_N + j;
            #pragma unroll
            for (int i = 0; i < 8; i++) {
                float f = __uint_as_float(((q >> (4 * i)) & 15u) | 0x4B000000u);
                wrow[i * TILE_N] = s * (f - bz);
            }
        }
        __syncthreads();

        // ---- compute: 8 rows x 4 cols per thread via packed FFMA2 ----
        #pragma unroll 4
        for (int k = 0; k < K_TILE; k++) {
            ulonglong2 wv = *(const ulonglong2*)(ws + k * TILE_N + c * 4);
            const float* xr = xs + rb * K_TILE + k;
            #pragma unroll
            for (int i = 0; i < 8; i++) {
                unsigned long long xp = pack2dup(xr[i * K_TILE]);
                ffma2(acc[i][0], xp, wv.x);
                ffma2(acc[i][1], xp, wv.y);
            }
        }
        __syncthreads();
    }

    // ---- epilogue: partial sums to scratch (coalesced 16B stores) ----
    float* outp = g_part + split * (BATCH * OUT_DIM) + j0 + c * 4;
    #pragma unroll
    for (int i = 0; i < 8; i++) {
        ulonglong2 v;
        v.x = acc[i][0];
        v.y = acc[i][1];
        *(ulonglong2*)(outp + (rb + i) * OUT_DIM) = v;
    }
}

__global__ void reduce_bias(const float* __restrict__ bias,
                            float* __restrict__ out)
{
    const int N4 = BATCH * OUT_DIM / 4;   // 229376
    int i = blockIdx.x * blockDim.x + threadIdx.x;
    if (i >= N4) return;
    int col4 = i % (OUT_DIM / 4);
    float4 b4 = ((const float4*)bias)[col4];
    float4 s0 = ((const float4*)g_part)[i];
    float4 s1 = ((const float4*)g_part)[N4 + i];
    float4 s2 = ((const float4*)g_part)[2 * N4 + i];
    float4 s3 = ((const float4*)g_part)[3 * N4 + i];
    float4 o;
    o.x = s0.x + s1.x + s2.x + s3.x + b4.x;
    o.y = s0.y + s1.y + s2.y + s3.y + b4.y;
    o.z = s0.z + s1.z + s2.z + s3.z + b4.z;
    o.w = s0.w + s1.w + s2.w + s3.w + b4.w;
    ((float4*)out)[i] = o;
}

extern "C" void kernel_launch(void* const* d_in, const int* in_sizes, int n_in,
                              void* d_out, int out_size)
{
    const float* x       = (const float*)d_in[0];
    const int*   qweight = (const int*)  d_in[1];
    const int*   qzeros  = (const int*)  d_in[2];
    const float* scales  = (const float*)d_in[3];
    const float* bias    = (const float*)d_in[4];
    const int*   g_idx   = (const int*)  d_in[5];
    float*       out     = (float*)d_out;

    const int smem_bytes = (K_TILE * TILE_N + BATCH * K_TILE) * (int)sizeof(float); // 96 KB
    cudaFuncSetAttribute(gptq_gemm, cudaFuncAttributeMaxDynamicSharedMemorySize, smem_bytes);

    dim3 grid(OUT_DIM / TILE_N, KSPLIT);   // (112, 4)
    gptq_gemm<<<grid, THREADS, smem_bytes>>>(x, qweight, qzeros, scales, g_idx);

    const int N4 = BATCH * OUT_DIM / 4;
    reduce_bias<<<(N4 + 255) / 256, 256>>>(bias, out);
}

// round 9
// speedup vs baseline: 3.0074x; 3.0074x over previous
#include <cuda_runtime.h>
#include <cuda_fp16.h>
#include <cstdint>

// GPTQ 4-bit quant linear via base-ISA tensor cores (mma.sync m16n8k16 f16).
// out[64,14336] = x[64,4096] @ (s*(w-z)) + bias
// Per group g (128 k): facc[j,b] += s[g,j] * sum_k (w-z)*(xh+xl)
// (w-z) exact in fp16 (magic 0x6400 bias minus per-column 0x6400+z).
// x split into fp16 hi+lo; both passes accumulate into fp32 registers.

#define IN_DIM   4096
#define OUT_DIM  14336
#define BATCH    64
#define GROUPS   32
#define TILE_N   64
#define THREADS  256

// ---- static scratch (no allocs) ----
__device__ __align__(16) __half g_xh[BATCH * IN_DIM];
__device__ __align__(16) __half g_xl[BATCH * IN_DIM];

// ---- smem layout (bytes from dynamic base) ----
#define SM_S   0          // 64 scales (fp32)
#define SM_W   1024       // W tile: 64 rows(j) x 128 k fp16 = 16384
#define SM_XH  17408      // xh tile: 64 rows(b) x 128 k fp16 = 16384
#define SM_XL  33792      // xl tile: 16384
#define SMEM_TOTAL 50176

static __device__ __forceinline__ uint32_t smem_u32(const void* p) {
    uint32_t a;
    asm("{ .reg .u64 t; cvta.to.shared.u64 t, %1; cvt.u32.u64 %0, t; }"
        : "=r"(a) : "l"(p));
    return a;
}

#define LDMATRIX_X4(r0, r1, r2, r3, a) \
    asm volatile("ldmatrix.sync.aligned.m8n8.x4.shared.b16 {%0,%1,%2,%3}, [%4];" \
                 : "=r"(r0), "=r"(r1), "=r"(r2), "=r"(r3) : "r"(a))

#define MMA_16816(c, a0, a1, a2, a3, b0, b1) \
    asm volatile("mma.sync.aligned.m16n8k16.row.col.f32.f16.f16.f32 " \
                 "{%0,%1,%2,%3}, {%4,%5,%6,%7}, {%8,%9}, {%0,%1,%2,%3};" \
                 : "+f"((c)[0]), "+f"((c)[1]), "+f"((c)[2]), "+f"((c)[3]) \
                 : "r"(a0), "r"(a1), "r"(a2), "r"(a3), "r"(b0), "r"(b1))

// ---- prep: fp16 hi/lo split of x ----
__global__ void xprep(const float* __restrict__ x) {
    int i = blockIdx.x * blockDim.x + threadIdx.x;   // 0 .. B*IN-1
    float v = x[i];
    __half h = __float2half_rn(v);
    g_xh[i] = h;
    g_xl[i] = __float2half_rn(v - __half2float(h));
}

__global__ __launch_bounds__(THREADS, 2)
void gptq_mma(const int*   __restrict__ qweight,
              const int*   __restrict__ qzeros,
              const float* __restrict__ scales,
              const float* __restrict__ bias,
              const int*   __restrict__ g_idx,
              float*       __restrict__ out)
{
    extern __shared__ char smem[];
    const uint32_t sb  = smem_u32(smem);
    const int tid  = threadIdx.x;
    const int lane = tid & 31;
    const int wid  = tid >> 5;
    const int j0   = blockIdx.x * TILE_N;
    const int mbase = (wid & 1) * 32;    // batch-row tile of this warp
    const int nbase = (wid >> 1) * 16;   // out-col tile of this warp

    // per-lane ldmatrix address components (XOR-swizzled 16B chunks)
    const uint32_t aRow[2] = { (uint32_t)(mbase      + (lane & 15)) * 256u,
                               (uint32_t)(mbase + 16 + (lane & 15)) * 256u };
    const uint32_t aKH  = (uint32_t)(lane >> 4);          // k-half for A
    const uint32_t bRow = (uint32_t)(nbase + (lane & 7) + ((lane >> 4) << 3)) * 256u;
    const uint32_t bKH  = (uint32_t)((lane >> 3) & 1);    // k-half for B
    const uint32_t swz  = (uint32_t)(lane & 7);

    float facc[2][2][4];
    float gacc[2][2][4];
    #pragma unroll
    for (int mt = 0; mt < 2; ++mt)
        #pragma unroll
        for (int nt = 0; nt < 2; ++nt)
            #pragma unroll
            for (int i = 0; i < 4; ++i) { facc[mt][nt][i] = 0.f; gacc[mt][nt][i] = 0.f; }

    for (int g = 0; g < GROUPS; ++g) {
        const int gk0 = g * 128;
        const int gg  = g_idx[gk0];

        // ---- stage scales ----
        if (tid < TILE_N)
            *(float*)(smem + SM_S + tid * 4) = scales[gg * OUT_DIM + j0 + tid];

        // ---- dequant W tile: rows j (64) x 128 k fp16, (w - z) exact ----
        #pragma unroll
        for (int it = 0; it < 4; ++it) {
            int idx = tid + it * THREADS;      // 0..1023 packed words
            int j  = idx & 63;
            int kr = idx >> 6;                 // 16B k-chunk (8 k)
            uint32_t q  = (uint32_t)qweight[(gk0 / 8 + kr) * OUT_DIM + j0 + j];
            uint32_t zq = (uint32_t)qzeros[gg * (OUT_DIM / 8) + ((j0 + j) >> 3)];
            uint32_t z  = ((zq >> (((j0 + j) & 7) * 4)) & 15u) + 1u;
            uint32_t bz = 0x64006400u + z * 0x00010001u;        // (1024+z, 1024+z)
            uint32_t p0 = (q         & 0x000F000Fu) | 0x64006400u;  // (k0,k4)+1024
            uint32_t p1 = ((q >> 4)  & 0x000F000Fu) | 0x64006400u;  // (k1,k5)
            uint32_t p2 = ((q >> 8)  & 0x000F000Fu) | 0x64006400u;  // (k2,k6)
            uint32_t p3 = ((q >> 12) & 0x000F000Fu) | 0x64006400u;  // (k3,k7)
            asm("sub.f16x2 %0, %0, %1;" : "+r"(p0) : "r"(bz));      // w - z exact
            asm("sub.f16x2 %0, %0, %1;" : "+r"(p1) : "r"(bz));
            asm("sub.f16x2 %0, %0, %1;" : "+r"(p2) : "r"(bz));
            asm("sub.f16x2 %0, %0, %1;" : "+r"(p3) : "r"(bz));
            uint32_t w01, w23, w45, w67;
            asm("prmt.b32 %0, %1, %2, 0x5410;" : "=r"(w01) : "r"(p0), "r"(p1));
            asm("prmt.b32 %0, %1, %2, 0x5410;" : "=r"(w23) : "r"(p2), "r"(p3));
            asm("prmt.b32 %0, %1, %2, 0x7632;" : "=r"(w45) : "r"(p0), "r"(p1));
            asm("prmt.b32 %0, %1, %2, 0x7632;" : "=r"(w67) : "r"(p2), "r"(p3));
            uint32_t off = (uint32_t)j * 256u + (uint32_t)((kr ^ (j & 7)) * 16);
            *(uint4*)(smem + SM_W + off) = make_uint4(w01, w23, w45, w67);
        }

        // ---- stage x hi/lo tiles: 64 rows x 128 k fp16 each ----
        #pragma unroll
        for (int it = 0; it < 8; ++it) {
            int idx  = tid + it * THREADS;     // 0..2047 16B chunks
            int which = idx >> 10;             // 0 = hi, 1 = lo
            int rem  = idx & 1023;
            int row  = rem >> 4;
            int c    = rem & 15;
            const __half* src = which ? g_xl : g_xh;
            uint4 v = *(const uint4*)(src + row * IN_DIM + gk0 + c * 8);
            uint32_t off = (uint32_t)row * 256u + (uint32_t)((c ^ (row & 7)) * 16);
            *(uint4*)(smem + (which ? SM_XL : SM_XH) + off) = v;
        }
        __syncthreads();

        // ---- MMA: 2 passes (hi, lo) x 8 k-steps ----
        #pragma unroll
        for (int pass = 0; pass < 2; ++pass) {
            const uint32_t xb = sb + (pass ? SM_XL : SM_XH);
            #pragma unroll
            for (int ks = 0; ks < 8; ++ks) {
                uint32_t a0[4], a1[4], b[4];
                uint32_t aCh = ((2u * ks + aKH) ^ swz) * 16u;
                uint32_t bCh = ((2u * ks + bKH) ^ swz) * 16u;
                LDMATRIX_X4(a0[0], a0[1], a0[2], a0[3], xb + aRow[0] + aCh);
                LDMATRIX_X4(a1[0], a1[1], a1[2], a1[3], xb + aRow[1] + aCh);
                LDMATRIX_X4(b[0], b[1], b[2], b[3], sb + SM_W + bRow + bCh);
                MMA_16816(gacc[0][0], a0[0], a0[1], a0[2], a0[3], b[0], b[1]);
                MMA_16816(gacc[0][1], a0[0], a0[1], a0[2], a0[3], b[2], b[3]);
                MMA_16816(gacc[1][0], a1[0], a1[1], a1[2], a1[3], b[0], b[1]);
                MMA_16816(gacc[1][1], a1[0], a1[1], a1[2], a1[3], b[2], b[3]);
            }
        }

        // ---- fold per-group scale into fp32 accumulators ----
        {
            float2 s0 = *(float2*)(smem + SM_S + (nbase + (lane & 3) * 2) * 4);
            float2 s1 = *(float2*)(smem + SM_S + (nbase + 8 + (lane & 3) * 2) * 4);
            #pragma unroll
            for (int mt = 0; mt < 2; ++mt) {
                facc[mt][0][0] = fmaf(s0.x, gacc[mt][0][0], facc[mt][0][0]);
                facc[mt][0][1] = fmaf(s0.y, gacc[mt][0][1], facc[mt][0][1]);
                facc[mt][0][2] = fmaf(s0.x, gacc[mt][0][2], facc[mt][0][2]);
                facc[mt][0][3] = fmaf(s0.y, gacc[mt][0][3], facc[mt][0][3]);
                facc[mt][1][0] = fmaf(s1.x, gacc[mt][1][0], facc[mt][1][0]);
                facc[mt][1][1] = fmaf(s1.y, gacc[mt][1][1], facc[mt][1][1]);
                facc[mt][1][2] = fmaf(s1.x, gacc[mt][1][2], facc[mt][1][2]);
                facc[mt][1][3] = fmaf(s1.y, gacc[mt][1][3], facc[mt][1][3]);
                #pragma unroll
                for (int nt = 0; nt < 2; ++nt)
                    #pragma unroll
                    for (int i = 0; i < 4; ++i) gacc[mt][nt][i] = 0.f;
            }
        }
        __syncthreads();
    }

    // ---- epilogue: bias + store (8B vectorized) ----
    #pragma unroll
    for (int mt = 0; mt < 2; ++mt) {
        #pragma unroll
        for (int nt = 0; nt < 2; ++nt) {
            int n = j0 + nbase + nt * 8 + (lane & 3) * 2;
            float2 bv = *(const float2*)(bias + n);
            int m0 = mbase + mt * 16 + (lane >> 2);
            float2 v0 = make_float2(facc[mt][nt][0] + bv.x, facc[mt][nt][1] + bv.y);
            float2 v1 = make_float2(facc[mt][nt][2] + bv.x, facc[mt][nt][3] + bv.y);
            *(float2*)(out + (size_t)m0 * OUT_DIM + n)       = v0;
            *(float2*)(out + (size_t)(m0 + 8) * OUT_DIM + n) = v1;
        }
    }
}

extern "C" void kernel_launch(void* const* d_in, const int* in_sizes, int n_in,
                              void* d_out, int out_size)
{
    const float* x       = (const float*)d_in[0];
    const int*   qweight = (const int*)  d_in[1];
    const int*   qzeros  = (const int*)  d_in[2];
    const float* scales  = (const float*)d_in[3];
    const float* bias    = (const float*)d_in[4];
    const int*   g_idx   = (const int*)  d_in[5];
    float*       out     = (float*)d_out;

    xprep<<<(BATCH * IN_DIM) / 256, 256>>>(x);

    cudaFuncSetAttribute(gptq_mma, cudaFuncAttributeMaxDynamicSharedMemorySize,
                         SMEM_TOTAL);
    gptq_mma<<<OUT_DIM / TILE_N, THREADS, SMEM_TOTAL>>>(
        qweight, qzeros, scales, bias, g_idx, out);
}

// round 13
// speedup vs baseline: 3.0876x; 1.0267x over previous
#include <cuda_runtime.h>
#include <cuda_fp16.h>
#include <cstdint>

// GPTQ 4-bit quant linear via base-ISA tensor cores (mma.sync m16n8k16 f16).
// out[64,14336] = x[64,4096] @ (s*(w-z)) + bias
// Warp tiling: 8 warps = 2(m32) x 2(n32) x 2(k-half); k-halves reduced via
// smem at kernel end. (w-z) exact in fp16; x split hi+lo fp16, fp32 acc.

#define IN_DIM   4096
#define OUT_DIM  14336
#define BATCH    64
#define GROUPS   32
#define TILE_N   64
#define THREADS  256

// ---- static scratch (no allocs) ----
__device__ __align__(16) __half g_xh[BATCH * IN_DIM];
__device__ __align__(16) __half g_xl[BATCH * IN_DIM];

// ---- smem layout (bytes from dynamic base) ----
#define SM_S   0          // 64 scales (fp32)
#define SM_W   1024       // W tile: 64 rows(j) x 128 k fp16 = 16384 (reduce buf at end)
#define SM_XH  17408      // xh tile: 64 rows(b) x 128 k fp16 = 16384
#define SM_XL  33792      // xl tile: 16384
#define SMEM_TOTAL 50176

static __device__ __forceinline__ uint32_t smem_u32(const void* p) {
    uint32_t a;
    asm("{ .reg .u64 t; cvta.to.shared.u64 t, %1; cvt.u32.u64 %0, t; }"
        : "=r"(a) : "l"(p));
    return a;
}

#define LDMATRIX_X4(r0, r1, r2, r3, a) \
    asm volatile("ldmatrix.sync.aligned.m8n8.x4.shared.b16 {%0,%1,%2,%3}, [%4];" \
                 : "=r"(r0), "=r"(r1), "=r"(r2), "=r"(r3) : "r"(a))

#define MMA_16816(c, a0, a1, a2, a3, b0, b1) \
    asm volatile("mma.sync.aligned.m16n8k16.row.col.f32.f16.f16.f32 " \
                 "{%0,%1,%2,%3}, {%4,%5,%6,%7}, {%8,%9}, {%0,%1,%2,%3};" \
                 : "+f"((c)[0]), "+f"((c)[1]), "+f"((c)[2]), "+f"((c)[3]) \
                 : "r"(a0), "r"(a1), "r"(a2), "r"(a3), "r"(b0), "r"(b1))

// ---- prep: fp16 hi/lo split of x ----
__global__ void xprep(const float* __restrict__ x) {
    int i = blockIdx.x * blockDim.x + threadIdx.x;   // 0 .. B*IN-1
    float v = x[i];
    __half h = __float2half_rn(v);
    g_xh[i] = h;
    g_xl[i] = __float2half_rn(v - __half2float(h));
}

__global__ __launch_bounds__(THREADS, 2)
void gptq_mma(const int*   __restrict__ qweight,
              const int*   __restrict__ qzeros,
              const float* __restrict__ scales,
              const float* __restrict__ bias,
              const int*   __restrict__ g_idx,
              float*       __restrict__ out)
{
    extern __shared__ char smem[];
    const uint32_t sb  = smem_u32(smem);
    const int tid  = threadIdx.x;
    const int lane = tid & 31;
    const int wid  = tid >> 5;
    const int j0   = blockIdx.x * TILE_N;
    const int mbase = (wid & 1) * 32;          // batch-row tile of this warp
    const int nbase = ((wid >> 1) & 1) * 32;   // out-col tile of this warp
    const int khalf = wid >> 2;                // k-half (4 of 8 k-steps)

    // per-lane ldmatrix address components (XOR-swizzled 16B chunks)
    const uint32_t aRow[2] = { (uint32_t)(mbase      + (lane & 15)) * 256u,
                               (uint32_t)(mbase + 16 + (lane & 15)) * 256u };
    const uint32_t aKH  = (uint32_t)(lane >> 4);          // k-half for A frags
    const uint32_t bRow0 = (uint32_t)(nbase + (lane & 7) + ((lane >> 4) << 3)) * 256u;
    const uint32_t bRow1 = bRow0 + 16u * 256u;
    const uint32_t bKH  = (uint32_t)((lane >> 3) & 1);    // k-half for B frags
    const uint32_t swz  = (uint32_t)(lane & 7);

    float facc[2][4][4];
    float gacc[2][4][4];
    #pragma unroll
    for (int mt = 0; mt < 2; ++mt)
        #pragma unroll
        for (int nt = 0; nt < 4; ++nt)
            #pragma unroll
            for (int i = 0; i < 4; ++i) { facc[mt][nt][i] = 0.f; gacc[mt][nt][i] = 0.f; }

    for (int g = 0; g < GROUPS; ++g) {
        const int gk0 = g * 128;
        const int gg  = g_idx[gk0];

        // ---- stage scales ----
        if (tid < TILE_N)
            *(float*)(smem + SM_S + tid * 4) = scales[gg * OUT_DIM + j0 + tid];

        // ---- dequant W tile: rows j (64) x 128 k fp16, (w - z) exact ----
        #pragma unroll
        for (int it = 0; it < 4; ++it) {
            int idx = tid + it * THREADS;      // 0..1023 packed words
            int j  = idx & 63;
            int kr = idx >> 6;                 // 16B k-chunk (8 k)
            uint32_t q  = (uint32_t)qweight[(gk0 / 8 + kr) * OUT_DIM + j0 + j];
            uint32_t zq = (uint32_t)qzeros[gg * (OUT_DIM / 8) + ((j0 + j) >> 3)];
            uint32_t z  = ((zq >> (((j0 + j) & 7) * 4)) & 15u) + 1u;
            uint32_t bz = 0x64006400u + z * 0x00010001u;        // (1024+z, 1024+z)
            uint32_t p0 = (q         & 0x000F000Fu) | 0x64006400u;  // (k0,k4)+1024
            uint32_t p1 = ((q >> 4)  & 0x000F000Fu) | 0x64006400u;  // (k1,k5)
            uint32_t p2 = ((q >> 8)  & 0x000F000Fu) | 0x64006400u;  // (k2,k6)
            uint32_t p3 = ((q >> 12) & 0x000F000Fu) | 0x64006400u;  // (k3,k7)
            asm("sub.f16x2 %0, %0, %1;" : "+r"(p0) : "r"(bz));      // w - z exact
            asm("sub.f16x2 %0, %0, %1;" : "+r"(p1) : "r"(bz));
            asm("sub.f16x2 %0, %0, %1;" : "+r"(p2) : "r"(bz));
            asm("sub.f16x2 %0, %0, %1;" : "+r"(p3) : "r"(bz));
            uint32_t w01, w23, w45, w67;
            asm("prmt.b32 %0, %1, %2, 0x5410;" : "=r"(w01) : "r"(p0), "r"(p1));
            asm("prmt.b32 %0, %1, %2, 0x5410;" : "=r"(w23) : "r"(p2), "r"(p3));
            asm("prmt.b32 %0, %1, %2, 0x7632;" : "=r"(w45) : "r"(p0), "r"(p1));
            asm("prmt.b32 %0, %1, %2, 0x7632;" : "=r"(w67) : "r"(p2), "r"(p3));
            uint32_t off = (uint32_t)j * 256u + (uint32_t)((kr ^ (j & 7)) * 16);
            *(uint4*)(smem + SM_W + off) = make_uint4(w01, w23, w45, w67);
        }

        // ---- stage x hi/lo tiles: 64 rows x 128 k fp16 each ----
        #pragma unroll
        for (int it = 0; it < 8; ++it) {
            int idx  = tid + it * THREADS;     // 0..2047 16B chunks
            int which = idx >> 10;             // 0 = hi, 1 = lo
            int rem  = idx & 1023;
            int row  = rem >> 4;
            int c    = rem & 15;
            const __half* src = which ? g_xl : g_xh;
            uint4 v = *(const uint4*)(src + row * IN_DIM + gk0 + c * 8);
            uint32_t off = (uint32_t)row * 256u + (uint32_t)((c ^ (row & 7)) * 16);
            *(uint4*)(smem + (which ? SM_XL : SM_XH) + off) = v;
        }
        __syncthreads();

        // ---- MMA: 2 passes (hi, lo) x 4 k-steps (this warp's k-half) ----
        #pragma unroll
        for (int pass = 0; pass < 2; ++pass) {
            const uint32_t xb = sb + (pass ? SM_XL : SM_XH);
            #pragma unroll
            for (int ks4 = 0; ks4 < 4; ++ks4) {
                uint32_t ks = (uint32_t)(khalf * 4 + ks4);
                uint32_t a0[4], a1[4], b[8];
                uint32_t aCh = ((2u * ks + aKH) ^ swz) * 16u;
                uint32_t bCh = ((2u * ks + bKH) ^ swz) * 16u;
                LDMATRIX_X4(a0[0], a0[1], a0[2], a0[3], xb + aRow[0] + aCh);
                LDMATRIX_X4(a1[0], a1[1], a1[2], a1[3], xb + aRow[1] + aCh);
                LDMATRIX_X4(b[0], b[1], b[2], b[3], sb + SM_W + bRow0 + bCh);
                LDMATRIX_X4(b[4], b[5], b[6], b[7], sb + SM_W + bRow1 + bCh);
                #pragma unroll
                for (int nt = 0; nt < 4; ++nt) {
                    MMA_16816(gacc[0][nt], a0[0], a0[1], a0[2], a0[3], b[2*nt], b[2*nt+1]);
                    MMA_16816(gacc[1][nt], a1[0], a1[1], a1[2], a1[3], b[2*nt], b[2*nt+1]);
                }
            }
        }

        // ---- fold per-group scale into fp32 accumulators ----
        {
            float2 sv[4];
            #pragma unroll
            for (int nt = 0; nt < 4; ++nt)
                sv[nt] = *(float2*)(smem + SM_S + (nbase + nt * 8 + (lane & 3) * 2) * 4);
            #pragma unroll
            for (int mt = 0; mt < 2; ++mt)
                #pragma unroll
                for (int nt = 0; nt < 4; ++nt) {
                    facc[mt][nt][0] = fmaf(sv[nt].x, gacc[mt][nt][0], facc[mt][nt][0]);
                    facc[mt][nt][1] = fmaf(sv[nt].y, gacc[mt][nt][1], facc[mt][nt][1]);
                    facc[mt][nt][2] = fmaf(sv[nt].x, gacc[mt][nt][2], facc[mt][nt][2]);
                    facc[mt][nt][3] = fmaf(sv[nt].y, gacc[mt][nt][3], facc[mt][nt][3]);
                    gacc[mt][nt][0] = 0.f; gacc[mt][nt][1] = 0.f;
                    gacc[mt][nt][2] = 0.f; gacc[mt][nt][3] = 0.f;
                }
        }
        __syncthreads();
    }

    // ---- k-half reduce via smem (reuse W region; lane-contiguous layout) ----
    float* ff = &facc[0][0][0];
    if (khalf == 1) {
        int idx = wid - 4;
        #pragma unroll
        for (int i = 0; i < 32; ++i)
            *(float*)(smem + SM_W + (i * 128 + idx * 32 + lane) * 4) = ff[i];
    }
    __syncthreads();
    if (khalf == 0) {
        #pragma unroll
        for (int i = 0; i < 32; ++i)
            ff[i] += *(float*)(smem + SM_W + (i * 128 + wid * 32 + lane) * 4);

        // ---- epilogue: bias + store (8B vectorized) ----
        #pragma unroll
        for (int mt = 0; mt < 2; ++mt) {
            #pragma unroll
            for (int nt = 0; nt < 4; ++nt) {
                int n = j0 + nbase + nt * 8 + (lane & 3) * 2;
                float2 bv = *(const float2*)(bias + n);
                int m0 = mbase + mt * 16 + (lane >> 2);
                float2 v0 = make_float2(facc[mt][nt][0] + bv.x, facc[mt][nt][1] + bv.y);
                float2 v1 = make_float2(facc[mt][nt][2] + bv.x, facc[mt][nt][3] + bv.y);
                *(float2*)(out + (size_t)m0 * OUT_DIM + n)       = v0;
                *(float2*)(out + (size_t)(m0 + 8) * OUT_DIM + n) = v1;
            }
        }
    }
}

extern "C" void kernel_launch(void* const* d_in, const int* in_sizes, int n_in,
                              void* d_out, int out_size)
{
    const float* x       = (const float*)d_in[0];
    const int*   qweight = (const int*)  d_in[1];
    const int*   qzeros  = (const int*)  d_in[2];
    const float* scales  = (const float*)d_in[3];
    const float* bias    = (const float*)d_in[4];
    const int*   g_idx   = (const int*)  d_in[5];
    float*       out     = (float*)d_out;

    xprep<<<(BATCH * IN_DIM) / 256, 256>>>(x);

    cudaFuncSetAttribute(gptq_mma, cudaFuncAttributeMaxDynamicSharedMemorySize,
                         SMEM_TOTAL);
    gptq_mma<<<OUT_DIM / TILE_N, THREADS, SMEM_TOTAL>>>(
        qweight, qzeros, scales, bias, g_idx, out);
}

// round 17
// speedup vs baseline: 3.6328x; 1.1766x over previous
#include <cuda_runtime.h>
#include <cuda_fp16.h>
#include <cstdint>

// GPTQ 4-bit quant linear via base-ISA tensor cores (mma.sync m16n8k16 f16).
// out[64,14336] = x[64,4096] @ (s*(w-z)) + bias
// Pipelined: cp.async stages x tiles for group g+1 during group g's MMAs;
// W prefetched to regs, dequant+STS after MMA. Single accumulator bank kept
// in units of s_g via per-group rescale facc *= s_{g-1}/s_g; final *s_31.
// 8 warps = 2(m32) x 2(n32) x 2(k-half); k-halves reduced via smem at end.

#define IN_DIM   4096
#define OUT_DIM  14336
#define BATCH    64
#define GROUPS   32
#define TILE_N   64
#define THREADS  256

// ---- static scratch (no allocs) ----
__device__ __align__(16) __half g_xh[BATCH * IN_DIM];
__device__ __align__(16) __half g_xl[BATCH * IN_DIM];

// ---- smem layout (bytes from dynamic base; double buffered) ----
#define SM_S   0          // 2 x 64 scales (fp32) = 512
#define SM_W   1024       // 2 x 16384 (W tile; buf0 reused as reduce buffer)
#define SM_XH  33792      // 2 x 16384
#define SM_XL  66560      // 2 x 16384
#define SMEM_TOTAL 99328

static __device__ __forceinline__ uint32_t smem_u32(const void* p) {
    uint32_t a;
    asm("{ .reg .u64 t; cvta.to.shared.u64 t, %1; cvt.u32.u64 %0, t; }"
        : "=r"(a) : "l"(p));
    return a;
}

#define LDMATRIX_X4(r0, r1, r2, r3, a) \
    asm volatile("ldmatrix.sync.aligned.m8n8.x4.shared.b16 {%0,%1,%2,%3}, [%4];" \
                 : "=r"(r0), "=r"(r1), "=r"(r2), "=r"(r3) : "r"(a))

#define MMA_16816(c, a0, a1, a2, a3, b0, b1) \
    asm volatile("mma.sync.aligned.m16n8k16.row.col.f32.f16.f16.f32 " \
                 "{%0,%1,%2,%3}, {%4,%5,%6,%7}, {%8,%9}, {%0,%1,%2,%3};" \
                 : "+f"((c)[0]), "+f"((c)[1]), "+f"((c)[2]), "+f"((c)[3]) \
                 : "r"(a0), "r"(a1), "r"(a2), "r"(a3), "r"(b0), "r"(b1))

#define CP_ASYNC16(dst, src) \
    asm volatile("cp.async.cg.shared.global [%0], [%1], 16;" \
                 :: "r"(dst), "l"(src) : "memory")
#define CP_COMMIT() asm volatile("cp.async.commit_group;" ::: "memory")
#define CP_WAIT0()  asm volatile("cp.async.wait_group 0;" ::: "memory")

// ---- prep: fp16 hi/lo split of x ----
__global__ void xprep(const float* __restrict__ x) {
    int i = blockIdx.x * blockDim.x + threadIdx.x;
    float v = x[i];
    __half h = __float2half_rn(v);
    g_xh[i] = h;
    g_xl[i] = __float2half_rn(v - __half2float(h));
}

// prefetch next group's packed W + zeros into registers
static __device__ __forceinline__ void prefetch_wq(
    const int* __restrict__ qweight, const int* __restrict__ qzeros,
    int gg, int gk0, int j0, int tid, uint32_t* qf, uint32_t* zf)
{
    #pragma unroll
    for (int it = 0; it < 4; ++it) {
        int idx = tid + it * THREADS;
        int j = idx & 63, kr = idx >> 6;
        qf[it] = (uint32_t)qweight[(gk0 / 8 + kr) * OUT_DIM + j0 + j];
        zf[it] = (uint32_t)qzeros[gg * (OUT_DIM / 8) + ((j0 + j) >> 3)];
    }
}

// dequant prefetched W into smem buffer (w - z exact in fp16)
static __device__ __forceinline__ void store_w(
    char* smem, uint32_t wbase, int tid, int j0,
    const uint32_t* qf, const uint32_t* zf)
{
    #pragma unroll
    for (int it = 0; it < 4; ++it) {
        int idx = tid + it * THREADS;
        int j = idx & 63, kr = idx >> 6;
        uint32_t q = qf[it];
        uint32_t z = ((zf[it] >> (((j0 + j) & 7) * 4)) & 15u) + 1u;
        uint32_t bz = 0x64006400u + z * 0x00010001u;
        uint32_t p0 = (q         & 0x000F000Fu) | 0x64006400u;
        uint32_t p1 = ((q >> 4)  & 0x000F000Fu) | 0x64006400u;
        uint32_t p2 = ((q >> 8)  & 0x000F000Fu) | 0x64006400u;
        uint32_t p3 = ((q >> 12) & 0x000F000Fu) | 0x64006400u;
        asm("sub.f16x2 %0, %0, %1;" : "+r"(p0) : "r"(bz));
        asm("sub.f16x2 %0, %0, %1;" : "+r"(p1) : "r"(bz));
        asm("sub.f16x2 %0, %0, %1;" : "+r"(p2) : "r"(bz));
        asm("sub.f16x2 %0, %0, %1;" : "+r"(p3) : "r"(bz));
        uint32_t w01, w23, w45, w67;
        asm("prmt.b32 %0, %1, %2, 0x5410;" : "=r"(w01) : "r"(p0), "r"(p1));
        asm("prmt.b32 %0, %1, %2, 0x5410;" : "=r"(w23) : "r"(p2), "r"(p3));
        asm("prmt.b32 %0, %1, %2, 0x7632;" : "=r"(w45) : "r"(p0), "r"(p1));
        asm("prmt.b32 %0, %1, %2, 0x7632;" : "=r"(w67) : "r"(p2), "r"(p3));
        uint32_t off = (uint32_t)j * 256u + (uint32_t)((kr ^ (j & 7)) * 16);
        *(uint4*)(smem + wbase + off) = make_uint4(w01, w23, w45, w67);
    }
}

// async-stage x hi/lo tiles for one group
static __device__ __forceinline__ void stage_x(
    uint32_t sb, uint32_t buf_off, int tid, int gk0)
{
    #pragma unroll
    for (int it = 0; it < 8; ++it) {
        int idx = tid + it * THREADS;
        int which = idx >> 10;
        int rem = idx & 1023;
        int row = rem >> 4, c = rem & 15;
        const __half* src = (which ? g_xl : g_xh) + row * IN_DIM + gk0 + c * 8;
        uint32_t dst = sb + (which ? SM_XL : SM_XH) + buf_off
                     + (uint32_t)row * 256u + (uint32_t)((c ^ (row & 7)) * 16);
        CP_ASYNC16(dst, src);
    }
}

__global__ __launch_bounds__(THREADS, 2)
void gptq_mma(const int*   __restrict__ qweight,
              const int*   __restrict__ qzeros,
              const float* __restrict__ scales,
              const float* __restrict__ bias,
              const int*   __restrict__ g_idx,
              float*       __restrict__ out)
{
    extern __shared__ char smem[];
    const uint32_t sb  = smem_u32(smem);
    const int tid  = threadIdx.x;
    const int lane = tid & 31;
    const int wid  = tid >> 5;
    const int j0   = blockIdx.x * TILE_N;
    const int mbase = (wid & 1) * 32;
    const int nbase = ((wid >> 1) & 1) * 32;
    const int khalf = wid >> 2;

    const uint32_t aRow[2] = { (uint32_t)(mbase      + (lane & 15)) * 256u,
                               (uint32_t)(mbase + 16 + (lane & 15)) * 256u };
    const uint32_t aKH  = (uint32_t)(lane >> 4);
    const uint32_t bRow0 = (uint32_t)(nbase + (lane & 7) + ((lane >> 4) << 3)) * 256u;
    const uint32_t bRow1 = bRow0 + 16u * 256u;
    const uint32_t bKH  = (uint32_t)((lane >> 3) & 1);
    const uint32_t swz  = (uint32_t)(lane & 7);

    float facc[2][4][4];
    #pragma unroll
    for (int mt = 0; mt < 2; ++mt)
        #pragma unroll
        for (int nt = 0; nt < 4; ++nt)
            #pragma unroll
            for (int i = 0; i < 4; ++i) facc[mt][nt][i] = 0.f;
    float2 sP[4];

    // ---- prologue: stage group 0 into buf 0 ----
    uint32_t qf[4], zf[4];
    {
        int gg0 = g_idx[0];
        prefetch_wq(qweight, qzeros, gg0, 0, j0, tid, qf, zf);
        float sreg = (tid < 64) ? scales[gg0 * OUT_DIM + j0 + tid] : 0.f;
        stage_x(sb, 0, tid, 0);
        CP_COMMIT();
        store_w(smem, SM_W, tid, j0, qf, zf);
        if (tid < 64) *(float*)(smem + SM_S + tid * 4) = sreg;
        CP_WAIT0();
    }
    __syncthreads();

    for (int g = 0; g < GROUPS; ++g) {
        const int buf  = g & 1;
        const int nbuf = buf ^ 1;
        const bool have_next = (g + 1 < GROUPS);
        float sreg = 0.f;

        // ---- kick off next group's staging (async + reg prefetch) ----
        if (have_next) {
            int gk0n = (g + 1) * 128;
            int ggn  = g_idx[gk0n];
            prefetch_wq(qweight, qzeros, ggn, gk0n, j0, tid, qf, zf);
            if (tid < 64) sreg = scales[ggn * OUT_DIM + j0 + tid];
            stage_x(sb, (uint32_t)nbuf * 16384u, tid, gk0n);
            CP_COMMIT();
        }

        // ---- read this group's scales; rescale accumulator units ----
        {
            float2 sC[4];
            #pragma unroll
            for (int nt = 0; nt < 4; ++nt)
                sC[nt] = *(float2*)(smem + SM_S + buf * 256
                                    + (nbase + nt * 8 + (lane & 3) * 2) * 4);
            if (g) {
                #pragma unroll
                for (int nt = 0; nt < 4; ++nt) {
                    float rx = __fdividef(sP[nt].x, sC[nt].x);
                    float ry = __fdividef(sP[nt].y, sC[nt].y);
                    #pragma unroll
                    for (int mt = 0; mt < 2; ++mt) {
                        facc[mt][nt][0] *= rx; facc[mt][nt][1] *= ry;
                        facc[mt][nt][2] *= rx; facc[mt][nt][3] *= ry;
                    }
                }
            }
            #pragma unroll
            for (int nt = 0; nt < 4; ++nt) sP[nt] = sC[nt];
        }

        // ---- MMA on current buffer: 2 passes (hi, lo) x 4 k-steps ----
        const uint32_t wb = sb + SM_W + (uint32_t)buf * 16384u;
        #pragma unroll
        for (int pass = 0; pass < 2; ++pass) {
            const uint32_t xb = sb + (pass ? SM_XL : SM_XH) + (uint32_t)buf * 16384u;
            #pragma unroll
            for (int ks4 = 0; ks4 < 4; ++ks4) {
                uint32_t ks = (uint32_t)(khalf * 4 + ks4);
                uint32_t a0[4], a1[4], b[8];
                uint32_t aCh = ((2u * ks + aKH) ^ swz) * 16u;
                uint32_t bCh = ((2u * ks + bKH) ^ swz) * 16u;
                LDMATRIX_X4(a0[0], a0[1], a0[2], a0[3], xb + aRow[0] + aCh);
                LDMATRIX_X4(a1[0], a1[1], a1[2], a1[3], xb + aRow[1] + aCh);
                LDMATRIX_X4(b[0], b[1], b[2], b[3], wb + bRow0 + bCh);
                LDMATRIX_X4(b[4], b[5], b[6], b[7], wb + bRow1 + bCh);
                #pragma unroll
                for (int nt = 0; nt < 4; ++nt) {
                    MMA_16816(facc[0][nt], a0[0], a0[1], a0[2], a0[3], b[2*nt], b[2*nt+1]);
                    MMA_16816(facc[1][nt], a1[0], a1[1], a1[2], a1[3], b[2*nt], b[2*nt+1]);
                }
            }
        }

        // ---- finish next group's staging ----
        if (have_next) {
            store_w(smem, SM_W + (uint32_t)nbuf * 16384u, tid, j0, qf, zf);
            if (tid < 64) *(float*)(smem + SM_S + nbuf * 256 + tid * 4) = sreg;
            CP_WAIT0();
        }
        __syncthreads();
    }

    // ---- k-half reduce via smem (buf0 W region; lane-contiguous) ----
    float* ff = &facc[0][0][0];
    if (khalf == 1) {
        int idx = wid - 4;
        #pragma unroll
        for (int i = 0; i < 32; ++i)
            *(float*)(smem + SM_W + (i * 128 + idx * 32 + lane) * 4) = ff[i];
    }
    __syncthreads();
    if (khalf == 0) {
        #pragma unroll
        for (int i = 0; i < 32; ++i)
            ff[i] += *(float*)(smem + SM_W + (i * 128 + wid * 32 + lane) * 4);

        // ---- epilogue: fold final scale s_31, add bias, store ----
        #pragma unroll
        for (int mt = 0; mt < 2; ++mt) {
            #pragma unroll
            for (int nt = 0; nt < 4; ++nt) {
                int n = j0 + nbase + nt * 8 + (lane & 3) * 2;
                float2 bv = *(const float2*)(bias + n);
                int m0 = mbase + mt * 16 + (lane >> 2);
                float2 v0 = make_float2(fmaf(facc[mt][nt][0], sP[nt].x, bv.x),
                                        fmaf(facc[mt][nt][1], sP[nt].y, bv.y));
                float2 v1 = make_float2(fmaf(facc[mt][nt][2], sP[nt].x, bv.x),
                                        fmaf(facc[mt][nt][3], sP[nt].y, bv.y));
                *(float2*)(out + (size_t)m0 * OUT_DIM + n)       = v0;
                *(float2*)(out + (size_t)(m0 + 8) * OUT_DIM + n) = v1;
            }
        }
    }
}

extern "C" void kernel_launch(void* const* d_in, const int* in_sizes, int n_in,
                              void* d_out, int out_size)
{
    const float* x       = (const float*)d_in[0];
    const int*   qweight = (const int*)  d_in[1];
    const int*   qzeros  = (const int*)  d_in[2];
    const float* scales  = (const float*)d_in[3];
    const float* bias    = (const float*)d_in[4];
    const int*   g_idx   = (const int*)  d_in[5];
    float*       out     = (float*)d_out;

    xprep<<<(BATCH * IN_DIM) / 256, 256>>>(x);

    cudaFuncSetAttribute(gptq_mma, cudaFuncAttributeMaxDynamicSharedMemorySize,
                         SMEM_TOTAL);
    gptq_mma<<<OUT_DIM / TILE_N, THREADS, SMEM_TOTAL>>>(
        qweight, qzeros, scales, bias, g_idx, out);
}